// round 17
// baseline (speedup 1.0000x reference)
#include <cuda_runtime.h>

#define GN 4096   // N*N
#define TT 168    // T
#define BB 128    // B
#define NN 64     // N
#define PP 128    // P

#define ROWS_PER_BLK 8
#define MV_BLOCKS (GN / ROWS_PER_BLK)      // 512
#define TOTAL_K1  (MV_BLOCKS + BB)         // 640

#define ZB_BATCH  8
#define Z_BLOCKS  (BB / ZB_BATCH)          // 16 blocks  (minimal grid floor)
#define Z_THREADS 512

// Scratch (allocation-free rule: __device__ globals)
__device__ float d_v[GN];
__device__ float d_y[BB * NN];

__device__ __forceinline__ float dot4(float4 a, float4 b) {
    return a.x * b.x + a.y * b.y + a.z * b.z + a.w * b.w;
}

__device__ __forceinline__ float4 ldcg4(const float4* p) {
    float4 v;
    asm volatile("ld.global.cg.v4.f32 {%0,%1,%2,%3}, [%4];"
                 : "=f"(v.x), "=f"(v.y), "=f"(v.z), "=f"(v.w) : "l"(p));
    return v;
}

// ---------------------------------------------------------------------------
// Kernel 1 — EXACTLY the R4 design (proven 7.81us):
//  blocks [0, 512):  matvec, 8 rows/block, warp-per-row, w^2 staged in smem
//                    once per block. Fused F epilogue. v -> d_v.
//  blocks [512, 640): per-batch y[b,j] = sum_p x[b,j,p]*alpha[x_i[b,p]]
//                    (4 MB DRAM traffic overlaps matvec L2 traffic).
// ---------------------------------------------------------------------------
__global__ void __launch_bounds__(256) k_main(const float* __restrict__ g,
                                              const float* __restrict__ w,
                                              const float* __restrict__ alphas,
                                              const float* __restrict__ x,
                                              const int*   __restrict__ xi,
                                              float* __restrict__ Fout) {
    __shared__ __align__(16) float ws[GN];   // matvec: w^2 | y-block: ap reuse
    __shared__ float sal[TT];

    const int blk  = blockIdx.x;
    const int tid  = threadIdx.x;
    const int wid  = tid >> 5;
    const int lane = tid & 31;

    if (blk < MV_BLOCKS) {
        // ---- stage w^2 (16 KB) + alphas into smem ----
        const float4* __restrict__ w4g = reinterpret_cast<const float4*>(w);
        float4* ws4 = reinterpret_cast<float4*>(ws);
        #pragma unroll
        for (int k = 0; k < 4; k++) {
            float4 t = w4g[tid + k * 256];
            t.x *= t.x; t.y *= t.y; t.z *= t.z; t.w *= t.w;
            ws4[tid + k * 256] = t;
        }
        if (tid < TT) sal[tid] = alphas[tid];
        __syncthreads();

        // ---- warp-per-row dot product ----
        const int row = blk * ROWS_PER_BLK + wid;
        const float4* __restrict__ g4 =
            reinterpret_cast<const float4*>(g + (size_t)row * GN);

        float acc0 = 0.f, acc1 = 0.f, acc2 = 0.f, acc3 = 0.f;
        #pragma unroll
        for (int c = 0; c < 8; c++) {
            const int base = c * 128 + lane;          // float4 units
            float4 a0 = g4[base];       float4 a1 = g4[base + 32];
            float4 a2 = g4[base + 64];  float4 a3 = g4[base + 96];
            float4 b0 = ws4[base];      float4 b1 = ws4[base + 32];
            float4 b2 = ws4[base + 64]; float4 b3 = ws4[base + 96];
            acc0 += dot4(a0, b0);
            acc1 += dot4(a1, b1);
            acc2 += dot4(a2, b2);
            acc3 += dot4(a3, b3);
        }
        float s = (acc0 + acc1) + (acc2 + acc3);
        #pragma unroll
        for (int o = 16; o > 0; o >>= 1)
            s += __shfl_xor_sync(0xffffffffu, s, o);   // all lanes get sum

        if (lane == 0) d_v[row] = s;

        // ---- F epilogue: F[row, t] = v * alpha[t] ----
        float* __restrict__ Frow = Fout + (size_t)row * TT;
        #pragma unroll
        for (int t = lane; t < TT; t += 32)
            Frow[t] = s * sal[t];
    } else {
        // ---- y-block: batch b ----
        const int b = blk - MV_BLOCKS;
        float* ap = ws;   // reuse smem
        if (tid < PP)
            ap[tid] = alphas[xi[b * PP + tid]];
        __syncthreads();

        #pragma unroll
        for (int j = wid; j < NN; j += 8) {
            const float* __restrict__ xr = x + ((size_t)b * NN + j) * PP;
            float s = xr[lane]      * ap[lane]
                    + xr[lane + 32] * ap[lane + 32]
                    + xr[lane + 64] * ap[lane + 64]
                    + xr[lane + 96] * ap[lane + 96];
            #pragma unroll
            for (int o = 16; o > 0; o >>= 1)
                s += __shfl_xor_sync(0xffffffffu, s, o);
            if (lane == 0) d_y[b * NN + j] = s;
        }
    }
}

// ---------------------------------------------------------------------------
// Kernel 2 — minimal-grid tail (grid 16; floor scales with grid size):
// Z[b,i] = sum_j v[i*64+j] * y[b,j].
// Each block: 8 batches. Stage y (512 floats) coalesced, one load/thread.
// Thread (bq = tid>>6, i = tid&63) computes the FULL dot for Z[b0+bq, i]:
// 16 independent ldcg float4 of v row i (one L2 round trip, MLP=16),
// y from smem, 4 accumulators, plain store. No reduce, no sync after stage.
// ---------------------------------------------------------------------------
__global__ void __launch_bounds__(Z_THREADS) k_z(float* __restrict__ Zout) {
    __shared__ __align__(16) float sy[ZB_BATCH * NN];   // 512 floats

    const int b0  = blockIdx.x * ZB_BATCH;
    const int tid = threadIdx.x;

    sy[tid] = d_y[b0 * NN + tid];       // 512 threads = 512 floats, coalesced
    __syncthreads();

    const int bq = tid >> 6;            // batch within block 0..7
    const int i  = tid & 63;            // output row 0..63

    const float4* __restrict__ v4 =
        reinterpret_cast<const float4*>(d_v) + i * 16;
    const float4* __restrict__ y4 =
        reinterpret_cast<const float4*>(sy + bq * NN);

    float4 a0 = ldcg4(v4);      float4 a1 = ldcg4(v4 + 1);
    float4 a2 = ldcg4(v4 + 2);  float4 a3 = ldcg4(v4 + 3);
    float4 a4 = ldcg4(v4 + 4);  float4 a5 = ldcg4(v4 + 5);
    float4 a6 = ldcg4(v4 + 6);  float4 a7 = ldcg4(v4 + 7);
    float4 a8 = ldcg4(v4 + 8);  float4 a9 = ldcg4(v4 + 9);
    float4 aa = ldcg4(v4 + 10); float4 ab = ldcg4(v4 + 11);
    float4 ac = ldcg4(v4 + 12); float4 ad = ldcg4(v4 + 13);
    float4 ae = ldcg4(v4 + 14); float4 af = ldcg4(v4 + 15);

    float s0 = dot4(a0, y4[0])  + dot4(a1, y4[1])
             + dot4(a2, y4[2])  + dot4(a3, y4[3]);
    float s1 = dot4(a4, y4[4])  + dot4(a5, y4[5])
             + dot4(a6, y4[6])  + dot4(a7, y4[7]);
    float s2 = dot4(a8, y4[8])  + dot4(a9, y4[9])
             + dot4(aa, y4[10]) + dot4(ab, y4[11]);
    float s3 = dot4(ac, y4[12]) + dot4(ad, y4[13])
             + dot4(ae, y4[14]) + dot4(af, y4[15]);

    Zout[(b0 + bq) * NN + i] = (s0 + s1) + (s2 + s3);
}

// ---------------------------------------------------------------------------
extern "C" void kernel_launch(void* const* d_in, const int* in_sizes, int n_in,
                              void* d_out, int out_size) {
    const float* x      = (const float*)d_in[0];   // [B, N, P]
    const int*   xi     = (const int*)  d_in[1];   // [B, P]
    const float* g      = (const float*)d_in[2];   // [N*N, N*N]
    const float* w      = (const float*)d_in[3];   // [N*N, 1]
    const float* alphas = (const float*)d_in[4];   // [1, T]

    float* out = (float*)d_out;
    float* Z = out;               // [B, N]   = 8192
    float* F = out + BB * NN;     // [N*N, T] = 688128

    k_main<<<TOTAL_K1, 256>>>(g, w, alphas, x, xi, F);
    k_z<<<Z_BLOCKS, Z_THREADS>>>(Z);
}